// round 13
// baseline (speedup 1.0000x reference)
#include <cuda_runtime.h>
#include <cstdint>

using ull = unsigned long long;

#define VOC 95
#define TT  256
#define BB  2048

// ---------------- scratch: xp = x @ Wih1^T + bih1  [B*T, 96] ----------------
__device__ float g_xp[(size_t)BB * TT * 96];

// ---------- packed fp32x2 helpers ----------
__device__ __forceinline__ ull pk2(float w) {
    ull d; unsigned r = __float_as_uint(w);
    asm("mov.b64 %0, {%1,%1};" : "=l"(d) : "r"(r));
    return d;
}
__device__ __forceinline__ ull pkf(float a, float b) {
    ull d;
    asm("mov.b64 %0, {%1,%2};" : "=l"(d)
        : "r"(__float_as_uint(a)), "r"(__float_as_uint(b)));
    return d;
}
__device__ __forceinline__ float2 up2(ull v) {
    unsigned lo, hi;
    asm("mov.b64 {%0,%1}, %2;" : "=r"(lo), "=r"(hi) : "l"(v));
    return make_float2(__uint_as_float(lo), __uint_as_float(hi));
}
__device__ __forceinline__ void fma2(ull& d, ull a, ull b) {
    asm("fma.rn.f32x2 %0, %1, %2, %0;" : "+l"(d) : "l"(a), "l"(b));
}
__device__ __forceinline__ ull add2(ull a, ull b) {
    ull d; asm("add.rn.f32x2 %0, %1, %2;" : "=l"(d) : "l"(a), "l"(b));
    return d;
}

// ---------- activations ----------
__device__ __forceinline__ float tanhap(float v) {
    float r; asm("tanh.approx.f32 %0, %1;" : "=f"(r) : "f"(v)); return r;
}
__device__ __forceinline__ float fsig(float v) {
    return fmaf(tanhap(0.5f * v), 0.5f, 0.5f);
}

extern __shared__ float smem[];

// GMEM weight [3*32, isz] -> SMEM fp32 [g][c][lane][4]
__device__ __forceinline__ void load_wmat(float* dst, const float* __restrict__ src,
                                          int C, int isz, int tid, int nthr)
{
    int n = 3 * C * 128;
    for (int idx = tid; idx < n; idx += nthr) {
        int q = idx & 3, jj = (idx >> 2) & 31;
        int c = (idx >> 7) % C, g = idx / (C * 128);
        int i = c * 4 + q;
        dst[idx] = (i < isz) ? src[(g * 32 + jj) * isz + i] : 0.f;
    }
}

// ============================================================================
// Kernel 1: xp = x @ Wih1^T + bih1  (unchanged, proven)
// ============================================================================
#define K1_NB   256
#define K1_NT   256
#define K1_XS   9216
#define K1_SMEM_FLOATS (9216 + 8 * 8 * 96 * 2)
#define K1_SMEM_BYTES  (K1_SMEM_FLOATS * 4)

__global__ void __launch_bounds__(K1_NT, 2)
gru_xproj(const float* __restrict__ x,
          const float* __restrict__ Wih1,
          const float* __restrict__ bih1)
{
    const int tid = threadIdx.x;
    load_wmat(smem, Wih1, 24, VOC, tid, K1_NT);
    __syncthreads();

    const int w = tid >> 5, j = tid & 31;
    float2* xsw = (float2*)(smem + K1_XS) + (size_t)w * (8 * 96);

    const ull bR = pk2(bih1[j]), bZ = pk2(bih1[32 + j]), bN = pk2(bih1[64 + j]);
    const size_t pairBase = ((size_t)blockIdx.x * 8 + w) * 128;

#pragma unroll 1
    for (int it = 0; it < 16; it++) {
        const size_t p0 = pairBase + (size_t)it * 8;
#pragma unroll
        for (int p = 0; p < 8; p++) {
            size_t r0 = (p0 + p) * 2, r1 = r0 + 1;
#pragma unroll
            for (int k = 0; k < 3; k++) {
                int i = j + 32 * k;
                float a = 0.f, b = 0.f;
                if (i < VOC) {
                    a = __ldcs(x + r0 * VOC + i);
                    b = __ldcs(x + r1 * VOC + i);
                }
                xsw[p * 96 + i] = make_float2(a, b);
            }
        }
        __syncwarp();

        ull acc[8][3];
#pragma unroll
        for (int p = 0; p < 8; p++) { acc[p][0] = bR; acc[p][1] = bZ; acc[p][2] = bN; }

#pragma unroll 2
        for (int c = 0; c < 24; c++) {
            float4 wA = *(const float4*)(smem + ((0 * 24 + c) * 32 + j) * 4);
            float4 wB = *(const float4*)(smem + ((1 * 24 + c) * 32 + j) * 4);
            float4 wC = *(const float4*)(smem + ((2 * 24 + c) * 32 + j) * 4);
            ull a0 = pk2(wA.x), a1 = pk2(wA.y), a2 = pk2(wA.z), a3 = pk2(wA.w);
            ull b0 = pk2(wB.x), b1 = pk2(wB.y), b2 = pk2(wB.z), b3 = pk2(wB.w);
            ull c0 = pk2(wC.x), c1 = pk2(wC.y), c2 = pk2(wC.z), c3 = pk2(wC.w);
#pragma unroll
            for (int p = 0; p < 8; p++) {
                ulonglong2 x01 = *(const ulonglong2*)(xsw + p * 96 + 4 * c);
                ulonglong2 x23 = *(const ulonglong2*)(xsw + p * 96 + 4 * c + 2);
                fma2(acc[p][0], x01.x, a0); fma2(acc[p][0], x01.y, a1);
                fma2(acc[p][0], x23.x, a2); fma2(acc[p][0], x23.y, a3);
                fma2(acc[p][1], x01.x, b0); fma2(acc[p][1], x01.y, b1);
                fma2(acc[p][1], x23.x, b2); fma2(acc[p][1], x23.y, b3);
                fma2(acc[p][2], x01.x, c0); fma2(acc[p][2], x01.y, c1);
                fma2(acc[p][2], x23.x, c2); fma2(acc[p][2], x23.y, c3);
            }
        }

#pragma unroll
        for (int p = 0; p < 8; p++) {
            size_t r0 = (p0 + p) * 2, r1 = r0 + 1;
#pragma unroll
            for (int g = 0; g < 3; g++) {
                float2 v = up2(acc[p][g]);
                g_xp[r0 * 96 + g * 32 + j] = v.x;
                g_xp[r1 * 96 + g * 32 + j] = v.y;
            }
        }
        __syncwarp();
    }
}

// ============================================================================
// Kernel 2: producer/consumer pairing scan, P=4 pairs (8 rows) per warp.
// 128 blocks x 4 warps. wid 0,1 = A (L1h+L2, groups 0,1); wid 2,3 = B (L3+FC).
// Each warp reads only its own 3 weight matrices -> weight crossbar halved.
// ============================================================================
#define NT2 128
#define NB  128
#define NP  4      // pairs per warp

// float offsets
#define OW1H 0
#define OW2I 3072
#define OW2H 6144
#define OW3I 9216
#define OW3H 12288
#define OWFC 15360
#define OH1  18432     // float2 h1[2 grp][4 pair][32]          = 512 floats
#define OH2  18944     // float2 h2[2 grp][2 slot][4 pair][32]  = 1024 floats
#define OH3  19968     // float2 h3[2 grp][4 pair][32]          = 512 floats
#define OFLG 20480     // int flags[2 grp][8] (0 = A-count, 4 = B-count)
#define K2_SMEM_FLOATS 20496
#define K2_SMEM_BYTES  (K2_SMEM_FLOATS * 4)

// fp32 weights, 8 chunks, P pairs (pair p input at in + p*32)
template<int P>
__device__ __forceinline__ void proj3m(const float* __restrict__ W, int j,
                                       const float2* __restrict__ in,
                                       ull (&acc)[P][3])
{
#pragma unroll
    for (int c = 0; c < 8; c++) {
        float4 wA = *(const float4*)(W + ((0 * 8 + c) * 32 + j) * 4);
        float4 wB = *(const float4*)(W + ((1 * 8 + c) * 32 + j) * 4);
        float4 wC = *(const float4*)(W + ((2 * 8 + c) * 32 + j) * 4);
        ull a0 = pk2(wA.x), a1 = pk2(wA.y), a2 = pk2(wA.z), a3 = pk2(wA.w);
        ull b0 = pk2(wB.x), b1 = pk2(wB.y), b2 = pk2(wB.z), b3 = pk2(wB.w);
        ull c0 = pk2(wC.x), c1 = pk2(wC.y), c2 = pk2(wC.z), c3 = pk2(wC.w);
#pragma unroll
        for (int p = 0; p < P; p++) {
            ulonglong2 x01 = *(const ulonglong2*)(in + p * 32 + 4 * c);
            ulonglong2 x23 = *(const ulonglong2*)(in + p * 32 + 4 * c + 2);
            fma2(acc[p][0], x01.x, a0); fma2(acc[p][0], x01.y, a1);
            fma2(acc[p][0], x23.x, a2); fma2(acc[p][0], x23.y, a3);
            fma2(acc[p][1], x01.x, b0); fma2(acc[p][1], x01.y, b1);
            fma2(acc[p][1], x23.x, b2); fma2(acc[p][1], x23.y, b3);
            fma2(acc[p][2], x01.x, c0); fma2(acc[p][2], x01.y, c1);
            fma2(acc[p][2], x23.x, c2); fma2(acc[p][2], x23.y, c3);
        }
    }
}

__device__ __forceinline__ ull gru_pair(ull aR, ull aZ, ull aNx, ull aNh, ull h)
{
    float2 r2 = up2(aR), z2 = up2(aZ), nx = up2(aNx), nh = up2(aNh), hh = up2(h);
    float r0 = fsig(r2.x), r1 = fsig(r2.y);
    float z0 = fsig(z2.x), z1 = fsig(z2.y);
    float n0 = tanhap(nx.x + r0 * nh.x);
    float n1 = tanhap(nx.y + r1 * nh.y);
    float h0 = n0 + z0 * (hh.x - n0);
    float h1 = n1 + z1 * (hh.y - n1);
    return pkf(h0, h1);
}

__device__ __forceinline__ void wait_ge(volatile int* f, int target) {
    if (*f >= target) return;
    while (*f < target) __nanosleep(40);
}

__global__ void __launch_bounds__(NT2, 1)
gru_scan(const float* __restrict__ Whh1, const float* __restrict__ bhh1,
         const float* __restrict__ Wih2, const float* __restrict__ Whh2,
         const float* __restrict__ bih2, const float* __restrict__ bhh2,
         const float* __restrict__ Wih3, const float* __restrict__ Whh3,
         const float* __restrict__ bih3, const float* __restrict__ bhh3,
         const float* __restrict__ Wfc,  const float* __restrict__ bfc,
         float* __restrict__ out)
{
    const int tid = threadIdx.x;

    load_wmat(smem + OW1H, Whh1, 8, 32, tid, NT2);
    load_wmat(smem + OW2I, Wih2, 8, 32, tid, NT2);
    load_wmat(smem + OW2H, Whh2, 8, 32, tid, NT2);
    load_wmat(smem + OW3I, Wih3, 8, 32, tid, NT2);
    load_wmat(smem + OW3H, Whh3, 8, 32, tid, NT2);
    {
        float* dst = smem + OWFC;
        for (int idx = tid; idx < 3 * 8 * 128; idx += NT2) {
            int q = idx & 3, jj = (idx >> 2) & 31;
            int c = (idx >> 7) % 8, g = idx / (8 * 128);
            int o = g * 32 + jj, k = c * 4 + q;
            dst[idx] = (o < VOC) ? Wfc[o * 32 + k] : 0.f;
        }
    }
    // zero h states + rings + flags
    for (int idx = tid; idx < K2_SMEM_FLOATS - OH1; idx += NT2)
        smem[OH1 + idx] = 0.f;
    __syncthreads();

    const int w = tid >> 5, j = tid & 31;
    const int g = w & 1;
    const int rb = blockIdx.x * 16 + g * 8;   // this group's 8 rows
    float2* const h1b = (float2*)(smem + OH1) + g * 128;
    float2* const h2b = (float2*)(smem + OH2) + g * 256;
    float2* const h3b = (float2*)(smem + OH3) + g * 128;
    volatile int* const flg = (volatile int*)(smem + OFLG) + g * 8;

    if (w < 2) {
        // ===================== A: L1h + L2 for 4 pairs =====================
        ull bh1R = pk2(bhh1[j]), bh1Z = pk2(bhh1[32 + j]), bh1N = pk2(bhh1[64 + j]);
        ull bi2R = pk2(bih2[j]), bi2Z = pk2(bih2[32 + j]), bi2N = pk2(bih2[64 + j]);
        ull bh2R = pk2(bhh2[j]), bh2Z = pk2(bhh2[32 + j]), bh2N = pk2(bhh2[64 + j]);

        size_t xb[2 * NP];
#pragma unroll
        for (int r = 0; r < 2 * NP; r++) xb[r] = (size_t)(rb + r) * TT * 96;

        ull cur[NP][3];
#pragma unroll
        for (int p = 0; p < NP; p++)
#pragma unroll
            for (int gg = 0; gg < 3; gg++) {
                int o = gg * 32 + j;
                cur[p][gg] = pkf(__ldcs(g_xp + xb[2 * p] + o),
                                 __ldcs(g_xp + xb[2 * p + 1] + o));
            }

#pragma unroll 1
        for (int t = 0; t < TT; t++) {
            float nf[NP][3][2];
            const int tn = t + 1;
            if (tn < TT) {
                const size_t toff = (size_t)tn * 96;
#pragma unroll
                for (int p = 0; p < NP; p++)
#pragma unroll
                    for (int gg = 0; gg < 3; gg++) {
                        int o = gg * 32 + j;
                        nf[p][gg][0] = __ldcs(g_xp + xb[2 * p] + toff + o);
                        nf[p][gg][1] = __ldcs(g_xp + xb[2 * p + 1] + toff + o);
                    }
            }

            // ---- L1: hidden proj + ew with xp ----
            {
                ull acc[NP][3];
#pragma unroll
                for (int p = 0; p < NP; p++) {
                    acc[p][0] = bh1R; acc[p][1] = bh1Z; acc[p][2] = bh1N;
                }
                proj3m<NP>(smem + OW1H, j, h1b, acc);
                ull hold[NP];
#pragma unroll
                for (int p = 0; p < NP; p++) hold[p] = *(const ull*)(h1b + p * 32 + j);
                __syncwarp();
#pragma unroll
                for (int p = 0; p < NP; p++) {
                    ull n = gru_pair(add2(cur[p][0], acc[p][0]),
                                     add2(cur[p][1], acc[p][1]),
                                     cur[p][2], acc[p][2], hold[p]);
                    *(ull*)(h1b + p * 32 + j) = n;
                }
                __syncwarp();
            }

            // ---- L2: input proj over h1, hidden proj over h2[t-1] ring ----
            ull xi[NP][3];
#pragma unroll
            for (int p = 0; p < NP; p++) { xi[p][0] = bi2R; xi[p][1] = bi2Z; xi[p][2] = bi2N; }
            proj3m<NP>(smem + OW2I, j, h1b, xi);

            const float2* h2o = h2b + ((t - 1) & 1) * 128;
            ull ga[NP][3];
#pragma unroll
            for (int p = 0; p < NP; p++) { ga[p][0] = bh2R; ga[p][1] = bh2Z; ga[p][2] = bh2N; }
            proj3m<NP>(smem + OW2H, j, h2o, ga);

            ull m[NP];
#pragma unroll
            for (int p = 0; p < NP; p++) {
                ull ho = *(const ull*)(h2o + p * 32 + j);
                m[p] = gru_pair(add2(xi[p][0], ga[p][0]), add2(xi[p][1], ga[p][1]),
                                xi[p][2], ga[p][2], ho);
            }

            // B must be done reading slot t&1 (its step t-2)
            if (t >= 2) wait_ge(flg + 4, t - 1);
            float2* h2n = h2b + (t & 1) * 128;
#pragma unroll
            for (int p = 0; p < NP; p++) *(ull*)(h2n + p * 32 + j) = m[p];
            __threadfence_block();
            __syncwarp();
            if (j == 0) flg[0] = t + 1;

            if (tn < TT) {
#pragma unroll
                for (int p = 0; p < NP; p++)
#pragma unroll
                    for (int gg = 0; gg < 3; gg++)
                        cur[p][gg] = pkf(nf[p][gg][0], nf[p][gg][1]);
            }
        }
    } else {
        // ===================== B: L3 + FC (1 step behind) =====================
        ull bi3R = pk2(bih3[j]), bi3Z = pk2(bih3[32 + j]), bi3N = pk2(bih3[64 + j]);
        ull bh3R = pk2(bhh3[j]), bh3Z = pk2(bhh3[32 + j]), bh3N = pk2(bhh3[64 + j]);
        float bf0f = (j      < VOC) ? bfc[j]      : 0.f;
        float bf1f = (32 + j < VOC) ? bfc[32 + j] : 0.f;
        float bf2f = (64 + j < VOC) ? bfc[64 + j] : 0.f;
        ull bfc0 = pk2(bf0f), bfc1 = pk2(bf1f), bfc2 = pk2(bf2f);

#pragma unroll 1
        for (int s = 0; s < TT; s++) {
            wait_ge(flg, s + 1);
            __threadfence_block();

            // ---- L3 input proj over h2[s] ----
            const float2* h2s = h2b + (s & 1) * 128;
            ull xi[NP][3];
#pragma unroll
            for (int p = 0; p < NP; p++) { xi[p][0] = bi3R; xi[p][1] = bi3Z; xi[p][2] = bi3N; }
            proj3m<NP>(smem + OW3I, j, h2s, xi);
            __threadfence_block();
            __syncwarp();
            if (j == 0) flg[4] = s + 1;    // release h2 slot back to A

            // ---- L3 hidden proj + ew ----
            ull ga[NP][3];
#pragma unroll
            for (int p = 0; p < NP; p++) { ga[p][0] = bh3R; ga[p][1] = bh3Z; ga[p][2] = bh3N; }
            proj3m<NP>(smem + OW3H, j, h3b, ga);
            ull hold[NP];
#pragma unroll
            for (int p = 0; p < NP; p++) hold[p] = *(const ull*)(h3b + p * 32 + j);
            __syncwarp();
#pragma unroll
            for (int p = 0; p < NP; p++) {
                ull n = gru_pair(add2(xi[p][0], ga[p][0]), add2(xi[p][1], ga[p][1]),
                                 xi[p][2], ga[p][2], hold[p]);
                *(ull*)(h3b + p * 32 + j) = n;
            }
            __syncwarp();

            // ---- FC head ----
            ull acc[NP][3];
#pragma unroll
            for (int p = 0; p < NP; p++) { acc[p][0] = bfc0; acc[p][1] = bfc1; acc[p][2] = bfc2; }
            proj3m<NP>(smem + OWFC, j, h3b, acc);
#pragma unroll
            for (int p = 0; p < NP; p++) {
                size_t base0 = ((size_t)(rb + 2 * p)     * TT + s) * VOC;
                size_t base1 = ((size_t)(rb + 2 * p + 1) * TT + s) * VOC;
                float2 v;
                v = up2(acc[p][0]); __stcs(out + base0 + j, v.x);      __stcs(out + base1 + j, v.y);
                v = up2(acc[p][1]); __stcs(out + base0 + 32 + j, v.x); __stcs(out + base1 + 32 + j, v.y);
                if (64 + j < VOC) {
                    v = up2(acc[p][2]); __stcs(out + base0 + 64 + j, v.x); __stcs(out + base1 + 64 + j, v.y);
                }
            }
        }
    }
}

extern "C" void kernel_launch(void* const* d_in, const int* in_sizes, int n_in,
                              void* d_out, int out_size)
{
    const float* x    = (const float*)d_in[0];
    const float* Wih1 = (const float*)d_in[1];
    const float* Whh1 = (const float*)d_in[2];
    const float* bih1 = (const float*)d_in[3];
    const float* bhh1 = (const float*)d_in[4];
    const float* Wih2 = (const float*)d_in[5];
    const float* Whh2 = (const float*)d_in[6];
    const float* bih2 = (const float*)d_in[7];
    const float* bhh2 = (const float*)d_in[8];
    const float* Wih3 = (const float*)d_in[9];
    const float* Whh3 = (const float*)d_in[10];
    const float* bih3 = (const float*)d_in[11];
    const float* bhh3 = (const float*)d_in[12];
    const float* Wfc  = (const float*)d_in[13];
    const float* bfc  = (const float*)d_in[14];
    float* out = (float*)d_out;

    cudaFuncSetAttribute(gru_xproj, cudaFuncAttributeMaxDynamicSharedMemorySize,
                         K1_SMEM_BYTES);
    cudaFuncSetAttribute(gru_scan, cudaFuncAttributeMaxDynamicSharedMemorySize,
                         K2_SMEM_BYTES);

    gru_xproj<<<K1_NB, K1_NT, K1_SMEM_BYTES>>>(x, Wih1, bih1);
    gru_scan<<<NB, NT2, K2_SMEM_BYTES>>>(Whh1, bhh1,
                                         Wih2, Whh2, bih2, bhh2,
                                         Wih3, Whh3, bih3, bhh3,
                                         Wfc, bfc, out);
}

// round 15
// speedup vs baseline: 1.0217x; 1.0217x over previous
#include <cuda_runtime.h>
#include <cstdint>

using ull = unsigned long long;

#define VOC 95
#define TT  256
#define BB  2048

// ---------------- scratch: xp = x @ Wih1^T + bih1  [B*T, 96] ----------------
__device__ float g_xp[(size_t)BB * TT * 96];

// ---------- packed fp32x2 helpers ----------
__device__ __forceinline__ ull pk2(float w) {
    ull d; unsigned r = __float_as_uint(w);
    asm("mov.b64 %0, {%1,%1};" : "=l"(d) : "r"(r));
    return d;
}
__device__ __forceinline__ ull pkf(float a, float b) {
    ull d;
    asm("mov.b64 %0, {%1,%2};" : "=l"(d)
        : "r"(__float_as_uint(a)), "r"(__float_as_uint(b)));
    return d;
}
__device__ __forceinline__ float2 up2(ull v) {
    unsigned lo, hi;
    asm("mov.b64 {%0,%1}, %2;" : "=r"(lo), "=r"(hi) : "l"(v));
    return make_float2(__uint_as_float(lo), __uint_as_float(hi));
}
__device__ __forceinline__ void fma2(ull& d, ull a, ull b) {
    asm("fma.rn.f32x2 %0, %1, %2, %0;" : "+l"(d) : "l"(a), "l"(b));
}
__device__ __forceinline__ ull add2(ull a, ull b) {
    ull d; asm("add.rn.f32x2 %0, %1, %2;" : "=l"(d) : "l"(a), "l"(b));
    return d;
}

// ---------- activations ----------
__device__ __forceinline__ float tanhap(float v) {
    float r; asm("tanh.approx.f32 %0, %1;" : "=f"(r) : "f"(v)); return r;
}
__device__ __forceinline__ float fsig(float v) {
    return fmaf(tanhap(0.5f * v), 0.5f, 0.5f);
}

extern __shared__ float smem[];

// GMEM weight [3*32, isz] -> SMEM fp32 [g][c][lane][4]
__device__ __forceinline__ void load_wmat(float* dst, const float* __restrict__ src,
                                          int C, int isz, int tid, int nthr)
{
    int n = 3 * C * 128;
    for (int idx = tid; idx < n; idx += nthr) {
        int q = idx & 3, jj = (idx >> 2) & 31;
        int c = (idx >> 7) % C, g = idx / (C * 128);
        int i = c * 4 + q;
        dst[idx] = (i < isz) ? src[(g * 32 + jj) * isz + i] : 0.f;
    }
}

// ============================================================================
// Kernel 1: xp = x @ Wih1^T + bih1  (unchanged, proven ~210 us)
// ============================================================================
#define K1_NB   256
#define K1_NT   256
#define K1_XS   9216
#define K1_SMEM_FLOATS (9216 + 8 * 8 * 96 * 2)
#define K1_SMEM_BYTES  (K1_SMEM_FLOATS * 4)

__global__ void __launch_bounds__(K1_NT, 2)
gru_xproj(const float* __restrict__ x,
          const float* __restrict__ Wih1,
          const float* __restrict__ bih1)
{
    const int tid = threadIdx.x;
    load_wmat(smem, Wih1, 24, VOC, tid, K1_NT);
    __syncthreads();

    const int w = tid >> 5, j = tid & 31;
    float2* xsw = (float2*)(smem + K1_XS) + (size_t)w * (8 * 96);

    const ull bR = pk2(bih1[j]), bZ = pk2(bih1[32 + j]), bN = pk2(bih1[64 + j]);
    const size_t pairBase = ((size_t)blockIdx.x * 8 + w) * 128;

#pragma unroll 1
    for (int it = 0; it < 16; it++) {
        const size_t p0 = pairBase + (size_t)it * 8;
#pragma unroll
        for (int p = 0; p < 8; p++) {
            size_t r0 = (p0 + p) * 2, r1 = r0 + 1;
#pragma unroll
            for (int k = 0; k < 3; k++) {
                int i = j + 32 * k;
                float a = 0.f, b = 0.f;
                if (i < VOC) {
                    a = __ldcs(x + r0 * VOC + i);
                    b = __ldcs(x + r1 * VOC + i);
                }
                xsw[p * 96 + i] = make_float2(a, b);
            }
        }
        __syncwarp();

        ull acc[8][3];
#pragma unroll
        for (int p = 0; p < 8; p++) { acc[p][0] = bR; acc[p][1] = bZ; acc[p][2] = bN; }

#pragma unroll 2
        for (int c = 0; c < 24; c++) {
            float4 wA = *(const float4*)(smem + ((0 * 24 + c) * 32 + j) * 4);
            float4 wB = *(const float4*)(smem + ((1 * 24 + c) * 32 + j) * 4);
            float4 wC = *(const float4*)(smem + ((2 * 24 + c) * 32 + j) * 4);
            ull a0 = pk2(wA.x), a1 = pk2(wA.y), a2 = pk2(wA.z), a3 = pk2(wA.w);
            ull b0 = pk2(wB.x), b1 = pk2(wB.y), b2 = pk2(wB.z), b3 = pk2(wB.w);
            ull c0 = pk2(wC.x), c1 = pk2(wC.y), c2 = pk2(wC.z), c3 = pk2(wC.w);
#pragma unroll
            for (int p = 0; p < 8; p++) {
                ulonglong2 x01 = *(const ulonglong2*)(xsw + p * 96 + 4 * c);
                ulonglong2 x23 = *(const ulonglong2*)(xsw + p * 96 + 4 * c + 2);
                fma2(acc[p][0], x01.x, a0); fma2(acc[p][0], x01.y, a1);
                fma2(acc[p][0], x23.x, a2); fma2(acc[p][0], x23.y, a3);
                fma2(acc[p][1], x01.x, b0); fma2(acc[p][1], x01.y, b1);
                fma2(acc[p][1], x23.x, b2); fma2(acc[p][1], x23.y, b3);
                fma2(acc[p][2], x01.x, c0); fma2(acc[p][2], x01.y, c1);
                fma2(acc[p][2], x23.x, c2); fma2(acc[p][2], x23.y, c3);
            }
        }

#pragma unroll
        for (int p = 0; p < 8; p++) {
            size_t r0 = (p0 + p) * 2, r1 = r0 + 1;
#pragma unroll
            for (int g = 0; g < 3; g++) {
                float2 v = up2(acc[p][g]);
                g_xp[r0 * 96 + g * 32 + j] = v.x;
                g_xp[r1 * 96 + g * 32 + j] = v.y;
            }
        }
        __syncwarp();
    }
}

// ============================================================================
// Kernel 2: per-matrix warp pipeline. 128 blocks x 12 warps; 2 groups x 8 rows.
// Stages: S0=L1h+ew, S1=L2i, S2=L2h+ew, S3=L3i, S4=L3h+ew, S5=FC.
// Each warp owns one matrix (96 weight wf/step). Links = double-buffered rings
// with the R12-proven flag idiom. No partial sums, no named barriers.
// ============================================================================
#define NT2 384
#define NB  128

// float offsets
#define OW1H 0
#define OW2I 3072
#define OW2H 6144
#define OW3I 9216
#define OW3H 12288
#define OWFC 15360
#define PH1  18432   // float2 [2g][4p][32] = 512 floats
#define PH2  18944
#define PH3  19456
#define RR1  19968   // float2 [2g][2slot][4p][32]  = 1024 floats
#define RR2  20992   // float2 [2g][2slot][4p][3gate][32] = 3072 floats
#define RR3  24064   // 1024
#define RR4  25088   // 3072
#define RR5  28160   // 1024
#define OFLG 29184   // int [2g][16]
#define K2_SMEM_FLOATS 29216
#define K2_SMEM_BYTES  (K2_SMEM_FLOATS * 4)

// fp32 weights, 8 chunks, 4 pairs (pair stride 32 float2, broadcast inputs)
__device__ __forceinline__ void proj4(const float* __restrict__ W, int j,
                                      const float2* __restrict__ in,
                                      ull (&acc)[4][3])
{
#pragma unroll
    for (int c = 0; c < 8; c++) {
        float4 wA = *(const float4*)(W + ((0 * 8 + c) * 32 + j) * 4);
        float4 wB = *(const float4*)(W + ((1 * 8 + c) * 32 + j) * 4);
        float4 wC = *(const float4*)(W + ((2 * 8 + c) * 32 + j) * 4);
        ull a0 = pk2(wA.x), a1 = pk2(wA.y), a2 = pk2(wA.z), a3 = pk2(wA.w);
        ull b0 = pk2(wB.x), b1 = pk2(wB.y), b2 = pk2(wB.z), b3 = pk2(wB.w);
        ull c0 = pk2(wC.x), c1 = pk2(wC.y), c2 = pk2(wC.z), c3 = pk2(wC.w);
#pragma unroll
        for (int p = 0; p < 4; p++) {
            ulonglong2 x01 = *(const ulonglong2*)(in + p * 32 + 4 * c);
            ulonglong2 x23 = *(const ulonglong2*)(in + p * 32 + 4 * c + 2);
            fma2(acc[p][0], x01.x, a0); fma2(acc[p][0], x01.y, a1);
            fma2(acc[p][0], x23.x, a2); fma2(acc[p][0], x23.y, a3);
            fma2(acc[p][1], x01.x, b0); fma2(acc[p][1], x01.y, b1);
            fma2(acc[p][1], x23.x, b2); fma2(acc[p][1], x23.y, b3);
            fma2(acc[p][2], x01.x, c0); fma2(acc[p][2], x01.y, c1);
            fma2(acc[p][2], x23.x, c2); fma2(acc[p][2], x23.y, c3);
        }
    }
}

__device__ __forceinline__ ull gru_pair(ull aR, ull aZ, ull aNx, ull aNh, ull h)
{
    float2 r2 = up2(aR), z2 = up2(aZ), nx = up2(aNx), nh = up2(aNh), hh = up2(h);
    float r0 = fsig(r2.x), r1 = fsig(r2.y);
    float z0 = fsig(z2.x), z1 = fsig(z2.y);
    float n0 = tanhap(nx.x + r0 * nh.x);
    float n1 = tanhap(nx.y + r1 * nh.y);
    float h0 = n0 + z0 * (hh.x - n0);
    float h1 = n1 + z1 * (hh.y - n1);
    return pkf(h0, h1);
}

__device__ __forceinline__ void wait_ge(volatile int* f, int target) {
    if (*f >= target) return;
    while (*f < target) __nanosleep(40);
}

// -------- input-projection stage (S1 = L2i, S3 = L3i) --------
__device__ __forceinline__ void stage_ipr(const float* __restrict__ W, int j,
                                          const float* __restrict__ bias,
                                          const float2* ringIn, float2* ringOut,
                                          volatile int* f,
                                          int fiData, int fiFree, int foFree, int foData)
{
    const ull b0 = pk2(bias[j]), b1 = pk2(bias[32 + j]), b2 = pk2(bias[64 + j]);
#pragma unroll 1
    for (int t = 0; t < TT; t++) {
        wait_ge(f + fiData, t + 1);
        __threadfence_block();
        const float2* rs = ringIn + (t & 1) * 128;
        ull acc[4][3];
#pragma unroll
        for (int p = 0; p < 4; p++) { acc[p][0] = b0; acc[p][1] = b1; acc[p][2] = b2; }
        proj4(W, j, rs, acc);
        __threadfence_block(); __syncwarp();
        if (j == 0) f[fiFree] = t + 1;

        if (t >= 2) wait_ge(f + foFree, t - 1);
        float2* ro = ringOut + (t & 1) * 384;
#pragma unroll
        for (int p = 0; p < 4; p++)
#pragma unroll
            for (int gg = 0; gg < 3; gg++)
                *(ull*)(ro + (p * 3 + gg) * 32 + j) = acc[p][gg];
        __threadfence_block(); __syncwarp();
        if (j == 0) f[foData] = t + 1;
    }
}

// -------- hidden-recurrence stage (S2 = L2h, S4 = L3h) --------
__device__ __forceinline__ void stage_hr(const float* __restrict__ W, int j,
                                         const float* __restrict__ bias,
                                         const float2* ringIn, float2* ph, float2* ringOut,
                                         volatile int* f,
                                         int fiData, int fiFree, int foFree, int foData)
{
    const ull b0 = pk2(bias[j]), b1 = pk2(bias[32 + j]), b2 = pk2(bias[64 + j]);
#pragma unroll 1
    for (int t = 0; t < TT; t++) {
        wait_ge(f + fiData, t + 1);
        __threadfence_block();
        const float2* ri = ringIn + (t & 1) * 384;
        ull xi[4][3];
#pragma unroll
        for (int p = 0; p < 4; p++)
#pragma unroll
            for (int gg = 0; gg < 3; gg++)
                xi[p][gg] = *(const ull*)(ri + (p * 3 + gg) * 32 + j);
        __threadfence_block(); __syncwarp();
        if (j == 0) f[fiFree] = t + 1;

        ull acc[4][3];
#pragma unroll
        for (int p = 0; p < 4; p++) { acc[p][0] = b0; acc[p][1] = b1; acc[p][2] = b2; }
        proj4(W, j, ph, acc);
        ull hold[4];
#pragma unroll
        for (int p = 0; p < 4; p++) hold[p] = *(const ull*)(ph + p * 32 + j);
        __syncwarp();
        ull hn[4];
#pragma unroll
        for (int p = 0; p < 4; p++) {
            hn[p] = gru_pair(add2(xi[p][0], acc[p][0]), add2(xi[p][1], acc[p][1]),
                             xi[p][2], acc[p][2], hold[p]);
            *(ull*)(ph + p * 32 + j) = hn[p];
        }
        if (t >= 2) wait_ge(f + foFree, t - 1);
        float2* ro = ringOut + (t & 1) * 128;
#pragma unroll
        for (int p = 0; p < 4; p++) *(ull*)(ro + p * 32 + j) = hn[p];
        __threadfence_block(); __syncwarp();
        if (j == 0) f[foData] = t + 1;
    }
}

__global__ void __launch_bounds__(NT2, 1)
gru_scan(const float* __restrict__ Whh1, const float* __restrict__ bhh1,
         const float* __restrict__ Wih2, const float* __restrict__ Whh2,
         const float* __restrict__ bih2, const float* __restrict__ bhh2,
         const float* __restrict__ Wih3, const float* __restrict__ Whh3,
         const float* __restrict__ bih3, const float* __restrict__ bhh3,
         const float* __restrict__ Wfc,  const float* __restrict__ bfc,
         float* __restrict__ out)
{
    const int tid = threadIdx.x;

    load_wmat(smem + OW1H, Whh1, 8, 32, tid, NT2);
    load_wmat(smem + OW2I, Wih2, 8, 32, tid, NT2);
    load_wmat(smem + OW2H, Whh2, 8, 32, tid, NT2);
    load_wmat(smem + OW3I, Wih3, 8, 32, tid, NT2);
    load_wmat(smem + OW3H, Whh3, 8, 32, tid, NT2);
    {
        float* dst = smem + OWFC;
        for (int idx = tid; idx < 3 * 8 * 128; idx += NT2) {
            int q = idx & 3, jj = (idx >> 2) & 31;
            int c = (idx >> 7) % 8, g = idx / (8 * 128);
            int o = g * 32 + jj, k = c * 4 + q;
            dst[idx] = (o < VOC) ? Wfc[o * 32 + k] : 0.f;
        }
    }
    // zero private states + rings + flags (h0 = 0)
    for (int idx = tid; idx < K2_SMEM_FLOATS - PH1; idx += NT2)
        smem[PH1 + idx] = 0.f;
    __syncthreads();

    const int w = tid >> 5, j = tid & 31;
    // stage/group mapping: heavy stages (0,2,4) spread (2,2,1,1) over SMSPs
    const unsigned sp0 = (0u) | (4u << 4) | (2u << 8) | (4u << 12)
                       | (2u << 16) | (0u << 20) | (5u << 24) | (3u << 28); // w0..w7
    const unsigned sp1 = (1u) | (3u << 4) | (1u << 8) | (5u << 12);          // w8..w11
    const int stage = (w < 8) ? (int)((sp0 >> (4 * w)) & 0xF)
                              : (int)((sp1 >> (4 * (w - 8))) & 0xF);
    const int g = (3244 >> w) & 1;   // bits: w2,w3,w5,w7,w10,w11 = 1
    const int rb = blockIdx.x * 16 + g * 8;

    volatile int* const f = ((volatile int*)(smem + OFLG)) + g * 16;
    float2* const r1 = (float2*)(smem + RR1) + g * 256;
    float2* const r2 = (float2*)(smem + RR2) + g * 768;
    float2* const r3 = (float2*)(smem + RR3) + g * 256;
    float2* const r4 = (float2*)(smem + RR4) + g * 768;
    float2* const r5 = (float2*)(smem + RR5) + g * 256;

    if (stage == 0) {
        // ---- S0: L1 hidden proj + ew with xp (private h1 -> ring1) ----
        const ull b0 = pk2(bhh1[j]), b1 = pk2(bhh1[32 + j]), b2 = pk2(bhh1[64 + j]);
        float2* ph = (float2*)(smem + PH1) + g * 128;
        size_t xr[4][2];
#pragma unroll
        for (int p = 0; p < 4; p++) {
            xr[p][0] = (size_t)(rb + 2 * p) * TT * 96;
            xr[p][1] = (size_t)(rb + 2 * p + 1) * TT * 96;
        }
        ull cur[4][3];
#pragma unroll
        for (int p = 0; p < 4; p++)
#pragma unroll
            for (int gg = 0; gg < 3; gg++) {
                int o = gg * 32 + j;
                cur[p][gg] = pkf(__ldcs(g_xp + xr[p][0] + o),
                                 __ldcs(g_xp + xr[p][1] + o));
            }
#pragma unroll 1
        for (int t = 0; t < TT; t++) {
            float nf[4][3][2];
            const int tn = t + 1;
            if (tn < TT) {
                const size_t toff = (size_t)tn * 96;
#pragma unroll
                for (int p = 0; p < 4; p++)
#pragma unroll
                    for (int gg = 0; gg < 3; gg++) {
                        int o = gg * 32 + j;
                        nf[p][gg][0] = __ldcs(g_xp + xr[p][0] + toff + o);
                        nf[p][gg][1] = __ldcs(g_xp + xr[p][1] + toff + o);
                    }
            }
            ull acc[4][3];
#pragma unroll
            for (int p = 0; p < 4; p++) { acc[p][0] = b0; acc[p][1] = b1; acc[p][2] = b2; }
            proj4(smem + OW1H, j, ph, acc);
            ull hold[4];
#pragma unroll
            for (int p = 0; p < 4; p++) hold[p] = *(const ull*)(ph + p * 32 + j);
            __syncwarp();
            ull hn[4];
#pragma unroll
            for (int p = 0; p < 4; p++) {
                hn[p] = gru_pair(add2(cur[p][0], acc[p][0]), add2(cur[p][1], acc[p][1]),
                                 cur[p][2], acc[p][2], hold[p]);
                *(ull*)(ph + p * 32 + j) = hn[p];
            }
            if (t >= 2) wait_ge(f + 1, t - 1);
            float2* ro = r1 + (t & 1) * 128;
#pragma unroll
            for (int p = 0; p < 4; p++) *(ull*)(ro + p * 32 + j) = hn[p];
            __threadfence_block(); __syncwarp();
            if (j == 0) f[0] = t + 1;

            if (tn < TT) {
#pragma unroll
                for (int p = 0; p < 4; p++)
#pragma unroll
                    for (int gg = 0; gg < 3; gg++)
                        cur[p][gg] = pkf(nf[p][gg][0], nf[p][gg][1]);
            }
        }
    } else if (stage == 1) {
        stage_ipr(smem + OW2I, j, bih2, r1, r2, f, 0, 1, 3, 2);
    } else if (stage == 2) {
        stage_hr(smem + OW2H, j, bhh2, r2, (float2*)(smem + PH2) + g * 128, r3,
                 f, 2, 3, 5, 4);
    } else if (stage == 3) {
        stage_ipr(smem + OW3I, j, bih3, r3, r4, f, 4, 5, 7, 6);
    } else if (stage == 4) {
        stage_hr(smem + OW3H, j, bhh3, r4, (float2*)(smem + PH3) + g * 128, r5,
                 f, 6, 7, 9, 8);
    } else {
        // ---- S5: FC head from ring5 ----
        const ull b0 = pk2((j      < VOC) ? bfc[j]      : 0.f);
        const ull b1 = pk2((32 + j < VOC) ? bfc[32 + j] : 0.f);
        const ull b2 = pk2((64 + j < VOC) ? bfc[64 + j] : 0.f);
#pragma unroll 1
        for (int t = 0; t < TT; t++) {
            wait_ge(f + 8, t + 1);
            __threadfence_block();
            const float2* rs = r5 + (t & 1) * 128;
            ull acc[4][3];
#pragma unroll
            for (int p = 0; p < 4; p++) { acc[p][0] = b0; acc[p][1] = b1; acc[p][2] = b2; }
            proj4(smem + OWFC, j, rs, acc);
            __threadfence_block(); __syncwarp();
            if (j == 0) f[9] = t + 1;
#pragma unroll
            for (int p = 0; p < 4; p++) {
                size_t base0 = ((size_t)(rb + 2 * p)     * TT + t) * VOC;
                size_t base1 = ((size_t)(rb + 2 * p + 1) * TT + t) * VOC;
                float2 v;
                v = up2(acc[p][0]); __stcs(out + base0 + j, v.x);      __stcs(out + base1 + j, v.y);
                v = up2(acc[p][1]); __stcs(out + base0 + 32 + j, v.x); __stcs(out + base1 + 32 + j, v.y);
                if (64 + j < VOC) {
                    v = up2(acc[p][2]); __stcs(out + base0 + 64 + j, v.x); __stcs(out + base1 + 64 + j, v.y);
                }
            }
        }
    }
}

extern "C" void kernel_launch(void* const* d_in, const int* in_sizes, int n_in,
                              void* d_out, int out_size)
{
    const float* x    = (const float*)d_in[0];
    const float* Wih1 = (const float*)d_in[1];
    const float* Whh1 = (const float*)d_in[2];
    const float* bih1 = (const float*)d_in[3];
    const float* bhh1 = (const float*)d_in[4];
    const float* Wih2 = (const float*)d_in[5];
    const float* Whh2 = (const float*)d_in[6];
    const float* bih2 = (const float*)d_in[7];
    const float* bhh2 = (const float*)d_in[8];
    const float* Wih3 = (const float*)d_in[9];
    const float* Whh3 = (const float*)d_in[10];
    const float* bih3 = (const float*)d_in[11];
    const float* bhh3 = (const float*)d_in[12];
    const float* Wfc  = (const float*)d_in[13];
    const float* bfc  = (const float*)d_in[14];
    float* out = (float*)d_out;

    cudaFuncSetAttribute(gru_xproj, cudaFuncAttributeMaxDynamicSharedMemorySize,
                         K1_SMEM_BYTES);
    cudaFuncSetAttribute(gru_scan, cudaFuncAttributeMaxDynamicSharedMemorySize,
                         K2_SMEM_BYTES);

    gru_xproj<<<K1_NB, K1_NT, K1_SMEM_BYTES>>>(x, Wih1, bih1);
    gru_scan<<<NB, NT2, K2_SMEM_BYTES>>>(Whh1, bhh1,
                                         Wih2, Whh2, bih2, bhh2,
                                         Wih3, Whh3, bih3, bhh3,
                                         Wfc, bfc, out);
}

// round 17
// speedup vs baseline: 1.6561x; 1.6209x over previous
#include <cuda_runtime.h>
#include <cstdint>

using ull = unsigned long long;

#define VOC 95
#define TT  256
#define BB  2048

// ---------------- scratch: xp = x @ Wih1^T + bih1  [B*T, 96] ----------------
__device__ float g_xp[(size_t)BB * TT * 96];

// ---------- packed fp32x2 helpers ----------
__device__ __forceinline__ ull pk2(float w) {
    ull d; unsigned r = __float_as_uint(w);
    asm("mov.b64 %0, {%1,%1};" : "=l"(d) : "r"(r));
    return d;
}
__device__ __forceinline__ ull pkf(float a, float b) {
    ull d;
    asm("mov.b64 %0, {%1,%2};" : "=l"(d)
        : "r"(__float_as_uint(a)), "r"(__float_as_uint(b)));
    return d;
}
__device__ __forceinline__ float2 up2(ull v) {
    unsigned lo, hi;
    asm("mov.b64 {%0,%1}, %2;" : "=r"(lo), "=r"(hi) : "l"(v));
    return make_float2(__uint_as_float(lo), __uint_as_float(hi));
}
__device__ __forceinline__ void fma2(ull& d, ull a, ull b) {
    asm("fma.rn.f32x2 %0, %1, %2, %0;" : "+l"(d) : "l"(a), "l"(b));
}
__device__ __forceinline__ ull add2(ull a, ull b) {
    ull d; asm("add.rn.f32x2 %0, %1, %2;" : "=l"(d) : "l"(a), "l"(b));
    return d;
}

// ---------- activations ----------
__device__ __forceinline__ float tanhap(float v) {
    float r; asm("tanh.approx.f32 %0, %1;" : "=f"(r) : "f"(v)); return r;
}
__device__ __forceinline__ float fsig(float v) {
    return fmaf(tanhap(0.5f * v), 0.5f, 0.5f);
}

extern __shared__ float smem[];

// GMEM weight [3*32, isz] -> SMEM fp32 [g][c][lane][4]
__device__ __forceinline__ void load_wmat(float* dst, const float* __restrict__ src,
                                          int C, int isz, int tid, int nthr)
{
    int n = 3 * C * 128;
    for (int idx = tid; idx < n; idx += nthr) {
        int q = idx & 3, jj = (idx >> 2) & 31;
        int c = (idx >> 7) % C, g = idx / (C * 128);
        int i = c * 4 + q;
        dst[idx] = (i < isz) ? src[(g * 32 + jj) * isz + i] : 0.f;
    }
}

// ============================================================================
// Kernel 1: xp = x @ Wih1^T + bih1  (unchanged, proven ~210 us)
// ============================================================================
#define K1_NB   256
#define K1_NT   256
#define K1_XS   9216
#define K1_SMEM_FLOATS (9216 + 8 * 8 * 96 * 2)
#define K1_SMEM_BYTES  (K1_SMEM_FLOATS * 4)

__global__ void __launch_bounds__(K1_NT, 2)
gru_xproj(const float* __restrict__ x,
          const float* __restrict__ Wih1,
          const float* __restrict__ bih1)
{
    const int tid = threadIdx.x;
    load_wmat(smem, Wih1, 24, VOC, tid, K1_NT);
    __syncthreads();

    const int w = tid >> 5, j = tid & 31;
    float2* xsw = (float2*)(smem + K1_XS) + (size_t)w * (8 * 96);

    const ull bR = pk2(bih1[j]), bZ = pk2(bih1[32 + j]), bN = pk2(bih1[64 + j]);
    const size_t pairBase = ((size_t)blockIdx.x * 8 + w) * 128;

#pragma unroll 1
    for (int it = 0; it < 16; it++) {
        const size_t p0 = pairBase + (size_t)it * 8;
#pragma unroll
        for (int p = 0; p < 8; p++) {
            size_t r0 = (p0 + p) * 2, r1 = r0 + 1;
#pragma unroll
            for (int k = 0; k < 3; k++) {
                int i = j + 32 * k;
                float a = 0.f, b = 0.f;
                if (i < VOC) {
                    a = __ldcs(x + r0 * VOC + i);
                    b = __ldcs(x + r1 * VOC + i);
                }
                xsw[p * 96 + i] = make_float2(a, b);
            }
        }
        __syncwarp();

        ull acc[8][3];
#pragma unroll
        for (int p = 0; p < 8; p++) { acc[p][0] = bR; acc[p][1] = bZ; acc[p][2] = bN; }

#pragma unroll 2
        for (int c = 0; c < 24; c++) {
            float4 wA = *(const float4*)(smem + ((0 * 24 + c) * 32 + j) * 4);
            float4 wB = *(const float4*)(smem + ((1 * 24 + c) * 32 + j) * 4);
            float4 wC = *(const float4*)(smem + ((2 * 24 + c) * 32 + j) * 4);
            ull a0 = pk2(wA.x), a1 = pk2(wA.y), a2 = pk2(wA.z), a3 = pk2(wA.w);
            ull b0 = pk2(wB.x), b1 = pk2(wB.y), b2 = pk2(wB.z), b3 = pk2(wB.w);
            ull c0 = pk2(wC.x), c1 = pk2(wC.y), c2 = pk2(wC.z), c3 = pk2(wC.w);
#pragma unroll
            for (int p = 0; p < 8; p++) {
                ulonglong2 x01 = *(const ulonglong2*)(xsw + p * 96 + 4 * c);
                ulonglong2 x23 = *(const ulonglong2*)(xsw + p * 96 + 4 * c + 2);
                fma2(acc[p][0], x01.x, a0); fma2(acc[p][0], x01.y, a1);
                fma2(acc[p][0], x23.x, a2); fma2(acc[p][0], x23.y, a3);
                fma2(acc[p][1], x01.x, b0); fma2(acc[p][1], x01.y, b1);
                fma2(acc[p][1], x23.x, b2); fma2(acc[p][1], x23.y, b3);
                fma2(acc[p][2], x01.x, c0); fma2(acc[p][2], x01.y, c1);
                fma2(acc[p][2], x23.x, c2); fma2(acc[p][2], x23.y, c3);
            }
        }

#pragma unroll
        for (int p = 0; p < 8; p++) {
            size_t r0 = (p0 + p) * 2, r1 = r0 + 1;
#pragma unroll
            for (int g = 0; g < 3; g++) {
                float2 v = up2(acc[p][g]);
                g_xp[r0 * 96 + g * 32 + j] = v.x;
                g_xp[r1 * 96 + g * 32 + j] = v.y;
            }
        }
        __syncwarp();
    }
}

// ============================================================================
// Kernel 2: R12 pairing scan + one register-hosted matrix per warp.
// A-warp (wid 0-3): L1h + L2 for 4 rows, W2H in registers.
// B-warp (wid 4-7): L3 + FC, 1 step behind, W3H in registers.
// ============================================================================
#define NT2 256
#define NB  128

// float offsets (all fp32)
#define OW1H 0
#define OW2I 3072
#define OW2H 6144
#define OW3I 9216
#define OW3H 12288
#define OWFC 15360
#define OH1  18432
#define OH2  18944
#define OH3  19968
#define OFLG 20480
#define K2_SMEM_FLOATS 20512
#define K2_SMEM_BYTES  (K2_SMEM_FLOATS * 4)

// fp32 SMEM weights, 8 chunks, 2 packed pairs
__device__ __forceinline__ void proj3f(const float* __restrict__ W, int j,
                                       const float2* __restrict__ in0,
                                       const float2* __restrict__ in1,
                                       ull& aA0, ull& aB0, ull& aC0,
                                       ull& aA1, ull& aB1, ull& aC1)
{
#pragma unroll
    for (int c = 0; c < 8; c++) {
        float4 wA = *(const float4*)(W + ((0 * 8 + c) * 32 + j) * 4);
        float4 wB = *(const float4*)(W + ((1 * 8 + c) * 32 + j) * 4);
        float4 wC = *(const float4*)(W + ((2 * 8 + c) * 32 + j) * 4);
        ulonglong2 x01 = *(const ulonglong2*)(in0 + 4 * c);
        ulonglong2 x23 = *(const ulonglong2*)(in0 + 4 * c + 2);
        ulonglong2 y01 = *(const ulonglong2*)(in1 + 4 * c);
        ulonglong2 y23 = *(const ulonglong2*)(in1 + 4 * c + 2);
        ull w;
        w = pk2(wA.x); fma2(aA0, x01.x, w); fma2(aA1, y01.x, w);
        w = pk2(wA.y); fma2(aA0, x01.y, w); fma2(aA1, y01.y, w);
        w = pk2(wA.z); fma2(aA0, x23.x, w); fma2(aA1, y23.x, w);
        w = pk2(wA.w); fma2(aA0, x23.y, w); fma2(aA1, y23.y, w);
        w = pk2(wB.x); fma2(aB0, x01.x, w); fma2(aB1, y01.x, w);
        w = pk2(wB.y); fma2(aB0, x01.y, w); fma2(aB1, y01.y, w);
        w = pk2(wB.z); fma2(aB0, x23.x, w); fma2(aB1, y23.x, w);
        w = pk2(wB.w); fma2(aB0, x23.y, w); fma2(aB1, y23.y, w);
        w = pk2(wC.x); fma2(aC0, x01.x, w); fma2(aC1, y01.x, w);
        w = pk2(wC.y); fma2(aC0, x01.y, w); fma2(aC1, y01.y, w);
        w = pk2(wC.z); fma2(aC0, x23.x, w); fma2(aC1, y23.x, w);
        w = pk2(wC.w); fma2(aC0, x23.y, w); fma2(aC1, y23.y, w);
    }
}

// REGISTER-hosted weights (lane slice wr[96]), 8 chunks, 2 packed pairs
__device__ __forceinline__ void proj3r(const float (&wr)[96],
                                       const float2* __restrict__ in0,
                                       const float2* __restrict__ in1,
                                       ull& aA0, ull& aB0, ull& aC0,
                                       ull& aA1, ull& aB1, ull& aC1)
{
#pragma unroll
    for (int c = 0; c < 8; c++) {
        ulonglong2 x01 = *(const ulonglong2*)(in0 + 4 * c);
        ulonglong2 x23 = *(const ulonglong2*)(in0 + 4 * c + 2);
        ulonglong2 y01 = *(const ulonglong2*)(in1 + 4 * c);
        ulonglong2 y23 = *(const ulonglong2*)(in1 + 4 * c + 2);
        ull w;
        w = pk2(wr[(0 * 8 + c) * 4 + 0]); fma2(aA0, x01.x, w); fma2(aA1, y01.x, w);
        w = pk2(wr[(0 * 8 + c) * 4 + 1]); fma2(aA0, x01.y, w); fma2(aA1, y01.y, w);
        w = pk2(wr[(0 * 8 + c) * 4 + 2]); fma2(aA0, x23.x, w); fma2(aA1, y23.x, w);
        w = pk2(wr[(0 * 8 + c) * 4 + 3]); fma2(aA0, x23.y, w); fma2(aA1, y23.y, w);
        w = pk2(wr[(1 * 8 + c) * 4 + 0]); fma2(aB0, x01.x, w); fma2(aB1, y01.x, w);
        w = pk2(wr[(1 * 8 + c) * 4 + 1]); fma2(aB0, x01.y, w); fma2(aB1, y01.y, w);
        w = pk2(wr[(1 * 8 + c) * 4 + 2]); fma2(aB0, x23.x, w); fma2(aB1, y23.x, w);
        w = pk2(wr[(1 * 8 + c) * 4 + 3]); fma2(aB0, x23.y, w); fma2(aB1, y23.y, w);
        w = pk2(wr[(2 * 8 + c) * 4 + 0]); fma2(aC0, x01.x, w); fma2(aC1, y01.x, w);
        w = pk2(wr[(2 * 8 + c) * 4 + 1]); fma2(aC0, x01.y, w); fma2(aC1, y01.y, w);
        w = pk2(wr[(2 * 8 + c) * 4 + 2]); fma2(aC0, x23.x, w); fma2(aC1, y23.x, w);
        w = pk2(wr[(2 * 8 + c) * 4 + 3]); fma2(aC0, x23.y, w); fma2(aC1, y23.y, w);
    }
}

__device__ __forceinline__ ull gru_pair(ull aR, ull aZ, ull aNx, ull aNh, ull h)
{
    float2 r2 = up2(aR), z2 = up2(aZ), nx = up2(aNx), nh = up2(aNh), hh = up2(h);
    float r0 = fsig(r2.x), r1 = fsig(r2.y);
    float z0 = fsig(z2.x), z1 = fsig(z2.y);
    float n0 = tanhap(nx.x + r0 * nh.x);
    float n1 = tanhap(nx.y + r1 * nh.y);
    float h0 = n0 + z0 * (hh.x - n0);
    float h1 = n1 + z1 * (hh.y - n1);
    return pkf(h0, h1);
}

__device__ __forceinline__ void wait_ge(volatile int* f, int target) {
    if (*f >= target) return;
    while (*f < target) __nanosleep(40);
}

__global__ void __launch_bounds__(NT2, 1)
gru_scan(const float* __restrict__ Whh1, const float* __restrict__ bhh1,
         const float* __restrict__ Wih2, const float* __restrict__ Whh2,
         const float* __restrict__ bih2, const float* __restrict__ bhh2,
         const float* __restrict__ Wih3, const float* __restrict__ Whh3,
         const float* __restrict__ bih3, const float* __restrict__ bhh3,
         const float* __restrict__ Wfc,  const float* __restrict__ bfc,
         float* __restrict__ out)
{
    const int tid = threadIdx.x;

    load_wmat(smem + OW1H, Whh1, 8, 32, tid, NT2);
    load_wmat(smem + OW2I, Wih2, 8, 32, tid, NT2);
    load_wmat(smem + OW2H, Whh2, 8, 32, tid, NT2);
    load_wmat(smem + OW3I, Wih3, 8, 32, tid, NT2);
    load_wmat(smem + OW3H, Whh3, 8, 32, tid, NT2);
    {
        float* dst = smem + OWFC;
        for (int idx = tid; idx < 3 * 8 * 128; idx += NT2) {
            int q = idx & 3, jj = (idx >> 2) & 31;
            int c = (idx >> 7) % 8, g = idx / (8 * 128);
            int o = g * 32 + jj, k = c * 4 + q;
            dst[idx] = (o < VOC) ? Wfc[o * 32 + k] : 0.f;
        }
    }
    for (int idx = tid; idx < K2_SMEM_FLOATS - OH1; idx += NT2)
        smem[OH1 + idx] = 0.f;
    __syncthreads();

    const int w = tid >> 5, j = tid & 31;
    const int g = w & 3;
    const int rb = blockIdx.x * 16 + g * 4;
    float2* const h1b = (float2*)(smem + OH1) + g * 64;
    float2* const h2b = (float2*)(smem + OH2) + g * 128;
    float2* const h3b = (float2*)(smem + OH3) + g * 64;
    volatile int* const flg = (volatile int*)(smem + OFLG) + g * 8;

    // register-hosted matrix: A -> W2H, B -> W3H
    float wr[96];
    {
        const float* Wsrc = smem + ((w < 4) ? OW2H : OW3H);
#pragma unroll
        for (int k = 0; k < 24; k++) {
            float4 v = *(const float4*)(Wsrc + k * 128 + j * 4);
            wr[4 * k + 0] = v.x; wr[4 * k + 1] = v.y;
            wr[4 * k + 2] = v.z; wr[4 * k + 3] = v.w;
        }
    }

    if (w < 4) {
        // ===================== A: L1h + L2 =====================
        ull bh1R = pk2(bhh1[j]), bh1Z = pk2(bhh1[32 + j]), bh1N = pk2(bhh1[64 + j]);
        ull bi2R = pk2(bih2[j]), bi2Z = pk2(bih2[32 + j]), bi2N = pk2(bih2[64 + j]);
        ull bh2R = pk2(bhh2[j]), bh2Z = pk2(bhh2[32 + j]), bh2N = pk2(bhh2[64 + j]);

        const size_t xb0 = (size_t)(rb + 0) * TT * 96;
        const size_t xb1 = (size_t)(rb + 1) * TT * 96;
        const size_t xb2 = (size_t)(rb + 2) * TT * 96;
        const size_t xb3 = (size_t)(rb + 3) * TT * 96;

        ull cur[2][3];
#pragma unroll
        for (int gg = 0; gg < 3; gg++) {
            int o = gg * 32 + j;
            cur[0][gg] = pkf(__ldcs(g_xp + xb0 + o), __ldcs(g_xp + xb1 + o));
            cur[1][gg] = pkf(__ldcs(g_xp + xb2 + o), __ldcs(g_xp + xb3 + o));
        }

#pragma unroll 1
        for (int t = 0; t < TT; t++) {
            float nf[2][3][2];
            const int tn = t + 1;
            if (tn < TT) {
                const size_t toff = (size_t)tn * 96;
#pragma unroll
                for (int gg = 0; gg < 3; gg++) {
                    int o = gg * 32 + j;
                    nf[0][gg][0] = __ldcs(g_xp + xb0 + toff + o);
                    nf[0][gg][1] = __ldcs(g_xp + xb1 + toff + o);
                    nf[1][gg][0] = __ldcs(g_xp + xb2 + toff + o);
                    nf[1][gg][1] = __ldcs(g_xp + xb3 + toff + o);
                }
            }

            // ---- L1: hidden proj (SMEM weights) + ew with xp ----
            {
                ull hR0 = bh1R, hZ0 = bh1Z, hN0 = bh1N;
                ull hR1 = bh1R, hZ1 = bh1Z, hN1 = bh1N;
                proj3f(smem + OW1H, j, h1b, h1b + 32,
                       hR0, hZ0, hN0, hR1, hZ1, hN1);
                ull h0 = *(const ull*)(h1b + j);
                ull h1p = *(const ull*)(h1b + 32 + j);
                __syncwarp();
                ull n0 = gru_pair(add2(cur[0][0], hR0), add2(cur[0][1], hZ0),
                                  cur[0][2], hN0, h0);
                ull n1 = gru_pair(add2(cur[1][0], hR1), add2(cur[1][1], hZ1),
                                  cur[1][2], hN1, h1p);
                *(ull*)(h1b + j) = n0;
                *(ull*)(h1b + 32 + j) = n1;
                __syncwarp();
            }

            // ---- L2: input proj (SMEM), hidden proj (REGS) over h2[t-1] ----
            ull xR0 = bi2R, xZ0 = bi2Z, xN0 = bi2N;
            ull xR1 = bi2R, xZ1 = bi2Z, xN1 = bi2N;
            proj3f(smem + OW2I, j, h1b, h1b + 32, xR0, xZ0, xN0, xR1, xZ1, xN1);

            const float2* h2o = h2b + ((t - 1) & 1) * 64;
            ull gR0 = bh2R, gZ0 = bh2Z, gN0 = bh2N;
            ull gR1 = bh2R, gZ1 = bh2Z, gN1 = bh2N;
            proj3r(wr, h2o, h2o + 32, gR0, gZ0, gN0, gR1, gZ1, gN1);
            ull ho0 = *(const ull*)(h2o + j);
            ull ho1 = *(const ull*)(h2o + 32 + j);
            ull m0 = gru_pair(add2(xR0, gR0), add2(xZ0, gZ0), xN0, gN0, ho0);
            ull m1 = gru_pair(add2(xR1, gR1), add2(xZ1, gZ1), xN1, gN1, ho1);

            if (t >= 2) wait_ge(flg + 4, t - 1);
            float2* h2n = h2b + (t & 1) * 64;
            *(ull*)(h2n + j) = m0;
            *(ull*)(h2n + 32 + j) = m1;
            __threadfence_block();
            __syncwarp();
            if (j == 0) flg[0] = t + 1;

            if (tn < TT) {
#pragma unroll
                for (int gg = 0; gg < 3; gg++) {
                    cur[0][gg] = pkf(nf[0][gg][0], nf[0][gg][1]);
                    cur[1][gg] = pkf(nf[1][gg][0], nf[1][gg][1]);
                }
            }
        }
    } else {
        // ===================== B: L3 + FC (1 step behind) =====================
        ull bi3R = pk2(bih3[j]), bi3Z = pk2(bih3[32 + j]), bi3N = pk2(bih3[64 + j]);
        ull bh3R = pk2(bhh3[j]), bh3Z = pk2(bhh3[32 + j]), bh3N = pk2(bhh3[64 + j]);
        float bf0f = (j      < VOC) ? bfc[j]      : 0.f;
        float bf1f = (32 + j < VOC) ? bfc[32 + j] : 0.f;
        float bf2f = (64 + j < VOC) ? bfc[64 + j] : 0.f;
        ull bfc0 = pk2(bf0f), bfc1 = pk2(bf1f), bfc2 = pk2(bf2f);

#pragma unroll 1
        for (int s = 0; s < TT; s++) {
            wait_ge(flg, s + 1);
            __threadfence_block();

            // ---- L3 input proj (SMEM) over h2[s] ----
            const float2* h2s = h2b + (s & 1) * 64;
            ull xR0 = bi3R, xZ0 = bi3Z, xN0 = bi3N;
            ull xR1 = bi3R, xZ1 = bi3Z, xN1 = bi3N;
            proj3f(smem + OW3I, j, h2s, h2s + 32, xR0, xZ0, xN0, xR1, xZ1, xN1);
            __threadfence_block();
            __syncwarp();
            if (j == 0) flg[4] = s + 1;    // release h2 slot back to A

            // ---- L3 hidden proj (REGS) + ew ----
            ull gR0 = bh3R, gZ0 = bh3Z, gN0 = bh3N;
            ull gR1 = bh3R, gZ1 = bh3Z, gN1 = bh3N;
            proj3r(wr, h3b, h3b + 32, gR0, gZ0, gN0, gR1, gZ1, gN1);
            ull ho0 = *(const ull*)(h3b + j);
            ull ho1 = *(const ull*)(h3b + 32 + j);
            __syncwarp();
            ull n0 = gru_pair(add2(xR0, gR0), add2(xZ0, gZ0), xN0, gN0, ho0);
            ull n1 = gru_pair(add2(xR1, gR1), add2(xZ1, gZ1), xN1, gN1, ho1);
            *(ull*)(h3b + j) = n0;
            *(ull*)(h3b + 32 + j) = n1;
            __syncwarp();

            // ---- FC head (SMEM fp32 weights) ----
            ull a00 = bfc0, a10 = bfc1, a20 = bfc2;
            ull a01 = bfc0, a11 = bfc1, a21 = bfc2;
            proj3f(smem + OWFC, j, h3b, h3b + 32, a00, a10, a20, a01, a11, a21);
            float2 v;
            size_t base0 = ((size_t)(rb + 0) * TT + s) * VOC;
            size_t base1 = ((size_t)(rb + 1) * TT + s) * VOC;
            size_t base2 = ((size_t)(rb + 2) * TT + s) * VOC;
            size_t base3 = ((size_t)(rb + 3) * TT + s) * VOC;
            int o0 = j, o1 = 32 + j, o2 = 64 + j;
            v = up2(a00); __stcs(out + base0 + o0, v.x); __stcs(out + base1 + o0, v.y);
            v = up2(a01); __stcs(out + base2 + o0, v.x); __stcs(out + base3 + o0, v.y);
            v = up2(a10); __stcs(out + base0 + o1, v.x); __stcs(out + base1 + o1, v.y);
            v = up2(a11); __stcs(out + base2 + o1, v.x); __stcs(out + base3 + o1, v.y);
            if (o2 < VOC) {
                v = up2(a20); __stcs(out + base0 + o2, v.x); __stcs(out + base1 + o2, v.y);
                v = up2(a21); __stcs(out + base2 + o2, v.x); __stcs(out + base3 + o2, v.y);
            }
        }
    }
}

extern "C" void kernel_launch(void* const* d_in, const int* in_sizes, int n_in,
                              void* d_out, int out_size)
{
    const float* x    = (const float*)d_in[0];
    const float* Wih1 = (const float*)d_in[1];
    const float* Whh1 = (const float*)d_in[2];
    const float* bih1 = (const float*)d_in[3];
    const float* bhh1 = (const float*)d_in[4];
    const float* Wih2 = (const float*)d_in[5];
    const float* Whh2 = (const float*)d_in[6];
    const float* bih2 = (const float*)d_in[7];
    const float* bhh2 = (const float*)d_in[8];
    const float* Wih3 = (const float*)d_in[9];
    const float* Whh3 = (const float*)d_in[10];
    const float* bih3 = (const float*)d_in[11];
    const float* bhh3 = (const float*)d_in[12];
    const float* Wfc  = (const float*)d_in[13];
    const float* bfc  = (const float*)d_in[14];
    float* out = (float*)d_out;

    cudaFuncSetAttribute(gru_xproj, cudaFuncAttributeMaxDynamicSharedMemorySize,
                         K1_SMEM_BYTES);
    cudaFuncSetAttribute(gru_scan, cudaFuncAttributeMaxDynamicSharedMemorySize,
                         K2_SMEM_BYTES);

    gru_xproj<<<K1_NB, K1_NT, K1_SMEM_BYTES>>>(x, Wih1, bih1);
    gru_scan<<<NB, NT2, K2_SMEM_BYTES>>>(Whh1, bhh1,
                                         Wih2, Whh2, bih2, bhh2,
                                         Wih3, Whh3, bih3, bhh3,
                                         Wfc, bfc, out);
}